// round 13
// baseline (speedup 1.0000x reference)
#include <cuda_runtime.h>
#include <cuda_fp16.h>
#include <cstdint>
#include <math.h>

// Problem constants
#define BATCH 256
#define NV    196
#define LT    32
#define CV    768
#define CT    512
#define CI    768
#define NHEAD 12
#define DHEAD 64

#define MQ  (BATCH*NV)   // 50176
#define MKV (BATCH*LT)   // 8192
#define NKV 1536         // combined K|V projection width

// Scratch (allocation-free rule: __device__ globals) — fp16 intermediates
__device__ __half2 g_qh[(size_t)MQ * (CI/2)];
__device__ __half2 g_kvh[(size_t)MKV * (NKV/2)];
__device__ __half2 g_ctxh[(size_t)MQ * (CI/2)];
__device__ float   g_part[(size_t)3 * MQ * 2];
// fp16 weights pre-packed in mma-fragment order
__device__ uint2 g_wkvF[(size_t)(CT/16) * (NKV/8) * 32];
__device__ uint2 g_wqF[(size_t)(CV/16) * (CI/8) * 32];
__device__ uint2 g_w1F[(size_t)(CI/16) * (CI/8) * 32];
__device__ float g_bkv[NKV];

// ---------------------------------------------------------------------------
__device__ __forceinline__ void mma_f16(float* c, const unsigned* a, const unsigned* b) {
    asm volatile(
        "mma.sync.aligned.m16n8k16.row.col.f32.f16.f16.f32 "
        "{%0,%1,%2,%3}, {%4,%5,%6,%7}, {%8,%9}, {%0,%1,%2,%3};\n"
        : "+f"(c[0]), "+f"(c[1]), "+f"(c[2]), "+f"(c[3])
        : "r"(a[0]), "r"(a[1]), "r"(a[2]), "r"(a[3]), "r"(b[0]), "r"(b[1]));
}
__device__ __forceinline__ unsigned h2u(const __half2 h) { return *(const unsigned*)&h; }
__device__ __forceinline__ void ldmatrix_x4(unsigned* r, unsigned addr) {
    asm volatile("ldmatrix.sync.aligned.m8n8.x4.shared.b16 {%0,%1,%2,%3}, [%4];"
        : "=r"(r[0]), "=r"(r[1]), "=r"(r[2]), "=r"(r[3]) : "r"(addr));
}

// ---------------------------------------------------------------------------
// Fused weight pack: blockIdx.y selects {Wk->kv, Wv->kv(+off), Wq, W1}.
// ---------------------------------------------------------------------------
__global__ void __launch_bounds__(256)
pack_all_kernel(const float* __restrict__ Wk, const float* __restrict__ Wv,
                const float* __restrict__ Wq, const float* __restrict__ W1,
                uint2* __restrict__ wkvF, uint2* __restrict__ wqF,
                uint2* __restrict__ w1F)
{
    const int which = blockIdx.y;
    const float* W;
    uint2* out;
    int K, outNtiles, tnOff;
    switch (which) {
        case 0: W = Wk; out = wkvF; K = CT; outNtiles = NKV/8; tnOff = 0;    break;
        case 1: W = Wv; out = wkvF; K = CT; outNtiles = NKV/8; tnOff = CI/8; break;
        case 2: W = Wq; out = wqF;  K = CV; outNtiles = CI/8;  tnOff = 0;    break;
        default:W = W1; out = w1F;  K = CI; outNtiles = CI/8;  tnOff = 0;    break;
    }
    const int N = CI;
    const int idx = blockIdx.x * 256 + threadIdx.x;
    const int total = (K / 16) * (N / 8) * 32;
    if (idx >= total) return;
    const int lane = idx & 31;
    const int tile = idx >> 5;
    const int ntiles = N / 8;
    const int tn = tile % ntiles;
    const int tk = tile / ntiles;
    const int g = lane >> 2, tig = lane & 3;
    const int n = tn * 8 + g;
    const int k0 = tk * 16 + 2 * tig;
    const __half2 b0 = __floats2half2_rn(W[(size_t)k0 * N + n], W[(size_t)(k0 + 1) * N + n]);
    const __half2 b1 = __floats2half2_rn(W[(size_t)(k0 + 8) * N + n], W[(size_t)(k0 + 9) * N + n]);
    uint2 r;
    r.x = h2u(b0);
    r.y = h2u(b1);
    out[((size_t)tk * outNtiles + tnOff + tn) * 32 + lane] = r;
}

// ---------------------------------------------------------------------------
// FP16 mma.sync GEMM (R9/R11-proven structure). Block 128x256, 8 warps,
// warp 64x64. A single-buffer smem + register staging, fragments via
// ldmatrix.x4; B fragment-order from global, register double-buffered.
// ADDVIS: A = ctx(fp16) + visA(fp32) fused at load (residual folded into MLP).
// ---------------------------------------------------------------------------
#define AS2_STRIDE 20

template <bool AHALF, bool MLPHEAD, bool ADDVIS>
__global__ void __launch_bounds__(256)
gemm_f16_kernel(const void* __restrict__ Aptr, const float* __restrict__ visA,
                const uint2* __restrict__ Bf,
                const float* __restrict__ bias, __half2* __restrict__ Ch,
                const float* __restrict__ W2, float* __restrict__ part,
                int M, int N, int K)
{
    __shared__ __half2 As[128 * AS2_STRIDE];
    __shared__ float red[4][128][2];   // only used when MLPHEAD

    const int tid = threadIdx.x;
    const int warp = tid >> 5, lane = tid & 31;
    const int g = lane >> 2, tig = lane & 3;
    const int wm = (warp >> 2) * 64;
    const int wnIdx = warp & 3;
    const int wn = wnIdx * 64;
    const int rowBase = blockIdx.y * 128;
    const int colBase = blockIdx.x * 256;
    const int Ntiles = N >> 3;
    const int tnBase = (colBase + wn) >> 3;

    const int lmRow = wm + (lane & 7) + ((lane >> 3) & 1) * 8;
    const int lmCol = (lane >> 4) * 4;
    const unsigned lmBase =
        (unsigned)__cvta_generic_to_shared(&As[lmRow * AS2_STRIDE + lmCol]);

    float acc[4][8][4];
#pragma unroll
    for (int mt = 0; mt < 4; mt++)
#pragma unroll
        for (int nt = 0; nt < 8; nt++)
#pragma unroll
            for (int r = 0; r < 4; r++) acc[mt][nt][r] = 0.f;

    const int KT = K >> 5;
    const int TKT = KT * 2;
    float4 ar[4];
    uint4 arh[2];
    float4 vr4[2][2];

    auto ldg_a = [&](int kt) {
        if (AHALF) {
            const __half2* Ah = (const __half2*)Aptr;
#pragma unroll
            for (int i = 0; i < 2; i++) {
                const int f = tid + i * 256;
                const int r = f >> 2, c4 = (f & 3) * 4;
                arh[i] = *(const uint4*)(Ah + (size_t)(rowBase + r) * (K / 2) + kt * 16 + c4);
                if (ADDVIS) {
                    const float* vp = visA + (size_t)(rowBase + r) * CV + kt * 32 + c4 * 2;
                    vr4[i][0] = *(const float4*)vp;
                    vr4[i][1] = *(const float4*)(vp + 4);
                }
            }
        } else {
            const float* Af = (const float*)Aptr;
#pragma unroll
            for (int i = 0; i < 4; i++) {
                const int f = tid + i * 256;
                const int r = f >> 3, c4 = (f & 7) * 4;
                ar[i] = *(const float4*)(Af + (size_t)(rowBase + r) * K + kt * 32 + c4);
            }
        }
    };

    uint2 bfr[2][8];
    {   // preload B fragments for tk = 0
        const uint2* bp = Bf + (size_t)tnBase * 32 + lane;
#pragma unroll
        for (int nt = 0; nt < 8; nt++) bfr[0][nt] = bp[nt * 32];
    }
    ldg_a(0);

    for (int kt = 0; kt < KT; kt++) {
        if (kt) __syncthreads();
        if (AHALF) {
#pragma unroll
            for (int i = 0; i < 2; i++) {
                const int f = tid + i * 256;
                const int r = f >> 2, c4 = (f & 3) * 4;
                uint4 v = arh[i];
                if (ADDVIS) {
                    const float* vf = (const float*)&vr4[i][0];
                    unsigned* vu = (unsigned*)&v;
#pragma unroll
                    for (int j = 0; j < 4; j++) {
                        const __half2 hh = *(const __half2*)&vu[j];
                        const float2 xf = __half22float2(hh);
                        vu[j] = h2u(__floats2half2_rn(xf.x + vf[2 * j], xf.y + vf[2 * j + 1]));
                    }
                }
                *(uint4*)&As[r * AS2_STRIDE + c4] = v;
            }
        } else {
#pragma unroll
            for (int i = 0; i < 4; i++) {
                const int f = tid + i * 256;
                const int r = f >> 3, c2 = (f & 7) * 2;
                const __half2 h0 = __floats2half2_rn(ar[i].x, ar[i].y);
                const __half2 h1 = __floats2half2_rn(ar[i].z, ar[i].w);
                __half2* dst = &As[r * AS2_STRIDE + c2];
                dst[0] = h0; dst[1] = h1;
            }
        }
        __syncthreads();

        if (kt + 1 < KT) ldg_a(kt + 1);

#pragma unroll
        for (int k16 = 0; k16 < 2; k16++) {
            const int tk = kt * 2 + k16;
            const int cur = tk & 1;
            if (tk + 1 < TKT) {
                const uint2* bp = Bf + ((size_t)(tk + 1) * Ntiles + tnBase) * 32 + lane;
#pragma unroll
                for (int nt = 0; nt < 8; nt++) bfr[cur ^ 1][nt] = bp[nt * 32];
            }
            unsigned a[4][4];
            const unsigned kOff = k16 * 8 * 4;
#pragma unroll
            for (int mt = 0; mt < 4; mt++)
                ldmatrix_x4(a[mt], lmBase + mt * 16 * AS2_STRIDE * 4 + kOff);
#pragma unroll
            for (int mt = 0; mt < 4; mt++)
#pragma unroll
                for (int nt = 0; nt < 8; nt++)
                    mma_f16(acc[mt][nt], a[mt], (const unsigned*)&bfr[cur][nt]);
        }
    }

    if (!MLPHEAD) {
        const int Nh = N >> 1;
#pragma unroll
        for (int mt = 0; mt < 4; mt++) {
            const int r0 = rowBase + wm + mt * 16 + g;
            const int r1 = r0 + 8;
#pragma unroll
            for (int nt = 0; nt < 8; nt++) {
                const int c = colBase + wn + nt * 8 + tig * 2;
                const float b0 = bias[c], b1 = bias[c + 1];
                Ch[(size_t)r0 * Nh + (c >> 1)] =
                    __floats2half2_rn(acc[mt][nt][0] + b0, acc[mt][nt][1] + b1);
                Ch[(size_t)r1 * Nh + (c >> 1)] =
                    __floats2half2_rn(acc[mt][nt][2] + b0, acc[mt][nt][3] + b1);
            }
        }
    } else {
#pragma unroll
        for (int mt = 0; mt < 4; mt++) {
            float h00 = 0.f, h01 = 0.f, h10 = 0.f, h11 = 0.f;
#pragma unroll
            for (int nt = 0; nt < 8; nt++) {
                const int c = colBase + wn + nt * 8 + tig * 2;
                const float b0 = bias[c], b1 = bias[c + 1];
                float v00 = acc[mt][nt][0] + b0, v01 = acc[mt][nt][1] + b1;
                float v10 = acc[mt][nt][2] + b0, v11 = acc[mt][nt][3] + b1;
                v00 = v00 / (1.f + __expf(-1.702f * v00));
                v01 = v01 / (1.f + __expf(-1.702f * v01));
                v10 = v10 / (1.f + __expf(-1.702f * v10));
                v11 = v11 / (1.f + __expf(-1.702f * v11));
                const float4 w4 = *(const float4*)(W2 + 2 * c);
                h00 += v00 * w4.x + v01 * w4.z;
                h01 += v00 * w4.y + v01 * w4.w;
                h10 += v10 * w4.x + v11 * w4.z;
                h11 += v10 * w4.y + v11 * w4.w;
            }
#pragma unroll
            for (int o = 1; o <= 2; o <<= 1) {
                h00 += __shfl_xor_sync(0xffffffff, h00, o);
                h01 += __shfl_xor_sync(0xffffffff, h01, o);
                h10 += __shfl_xor_sync(0xffffffff, h10, o);
                h11 += __shfl_xor_sync(0xffffffff, h11, o);
            }
            if (tig == 0) {
                const int rl = wm + mt * 16 + g;
                red[wnIdx][rl][0] = h00; red[wnIdx][rl][1] = h01;
                red[wnIdx][rl + 8][0] = h10; red[wnIdx][rl + 8][1] = h11;
            }
        }
        __syncthreads();
        const int rl = tid >> 1, o = tid & 1;
        const float s = red[0][rl][o] + red[1][rl][o] + red[2][rl][o] + red[3][rl][o];
        part[(size_t)blockIdx.x * MQ * 2 + (size_t)(rowBase + rl) * 2 + o] = s;
    }
}

// ---------------------------------------------------------------------------
// Tensor-core attention. TWO blocks per (b,h). Stores NORMALIZED ctx (fp16)
// only — the residual add moved into the MLP GEMM's A-loader.
// ---------------------------------------------------------------------------
__global__ void __launch_bounds__(128)
attn_kernel(const __half2* __restrict__ qh, const __half2* __restrict__ kvh,
            __half2* __restrict__ ctxh)
{
    __shared__ __half2 Qs[112 * 36];
    __shared__ __half2 Ks[32 * 36];
    __shared__ __half2 Vs[16 * 72];

    const int bh = blockIdx.x >> 1;
    const int chunk = blockIdx.x & 1;
    const int b = bh / NHEAD;
    const int h = bh % NHEAD;
    const int tid = threadIdx.x;
    const int warp = tid >> 5, lane = tid & 31;
    const int g = lane >> 2, tig = lane & 3;

    const int chunkBase = chunk * 112;
    const int nRows = chunk ? (NV - 112) : 112;
    const int numTiles = chunk ? 6 : 7;

    for (int f = tid; f < nRows * 8; f += 128) {
        const int n = f >> 3, c = f & 7;
        *(uint4*)&Qs[n * 36 + c * 4] =
            *(const uint4*)(qh + ((size_t)b * NV + chunkBase + n) * 384 + h * 32 + c * 4);
    }
    const int padRows = numTiles * 16 - nRows;
    for (int f = tid; f < padRows * 36; f += 128) {
        Qs[nRows * 36 + f] = __half2(__ushort_as_half(0), __ushort_as_half(0));
    }
    for (int f = tid; f < 32 * 8; f += 128) {
        const int l = f >> 3, c = f & 7;
        *(uint4*)&Ks[l * 36 + c * 4] =
            *(const uint4*)(kvh + ((size_t)b * LT + l) * 768 + h * 32 + c * 4);
    }
    __half* Vsh = (__half*)Vs;
    for (int f = tid; f < 32 * 32; f += 128) {
        const int l = f >> 5, d2 = f & 31;
        const __half2 val = kvh[((size_t)b * LT + l) * 768 + 384 + h * 32 + d2];
        const int base = (l >> 1) * 144 + 4 * d2 + (l & 1);
        Vsh[base] = __low2half(val);
        Vsh[base + 2] = __high2half(val);
    }
    __syncthreads();

    for (int t = warp; t < numTiles; t += 4) {
        const int mb = t * 16;
        float sc[4][4];
#pragma unroll
        for (int tl = 0; tl < 4; tl++)
#pragma unroll
            for (int j = 0; j < 4; j++) sc[tl][j] = 0.f;
#pragma unroll
        for (int td = 0; td < 4; td++) {
            unsigned a[4];
            a[0] = *(const unsigned*)&Qs[(mb + g) * 36 + 8 * td + tig];
            a[1] = *(const unsigned*)&Qs[(mb + 8 + g) * 36 + 8 * td + tig];
            a[2] = *(const unsigned*)&Qs[(mb + g) * 36 + 8 * td + tig + 4];
            a[3] = *(const unsigned*)&Qs[(mb + 8 + g) * 36 + 8 * td + tig + 4];
#pragma unroll
            for (int tl = 0; tl < 4; tl++) {
                unsigned bb[2];
                bb[0] = *(const unsigned*)&Ks[(8 * tl + g) * 36 + 8 * td + tig];
                bb[1] = *(const unsigned*)&Ks[(8 * tl + g) * 36 + 8 * td + tig + 4];
                mma_f16(sc[tl], a, bb);
            }
        }
        float mx0 = -1e30f, mx1 = -1e30f;
#pragma unroll
        for (int tl = 0; tl < 4; tl++) {
#pragma unroll
            for (int j = 0; j < 4; j++) sc[tl][j] *= 0.125f;
            mx0 = fmaxf(mx0, fmaxf(sc[tl][0], sc[tl][1]));
            mx1 = fmaxf(mx1, fmaxf(sc[tl][2], sc[tl][3]));
        }
        mx0 = fmaxf(mx0, __shfl_xor_sync(0xffffffff, mx0, 1));
        mx0 = fmaxf(mx0, __shfl_xor_sync(0xffffffff, mx0, 2));
        mx1 = fmaxf(mx1, __shfl_xor_sync(0xffffffff, mx1, 1));
        mx1 = fmaxf(mx1, __shfl_xor_sync(0xffffffff, mx1, 2));
        __half2 plo[4], phi[4];
        float sum0 = 0.f, sum1 = 0.f;
#pragma unroll
        for (int tl = 0; tl < 4; tl++) {
            const __half2 e0 = h2exp(__floats2half2_rn(sc[tl][0] - mx0, sc[tl][1] - mx0));
            const __half2 e1 = h2exp(__floats2half2_rn(sc[tl][2] - mx1, sc[tl][3] - mx1));
            plo[tl] = e0; phi[tl] = e1;
            const float2 f0 = __half22float2(e0);
            const float2 f1 = __half22float2(e1);
            sum0 += f0.x + f0.y;
            sum1 += f1.x + f1.y;
        }
        sum0 += __shfl_xor_sync(0xffffffff, sum0, 1);
        sum0 += __shfl_xor_sync(0xffffffff, sum0, 2);
        sum1 += __shfl_xor_sync(0xffffffff, sum1, 1);
        sum1 += __shfl_xor_sync(0xffffffff, sum1, 2);
        const float inv0 = __fdividef(1.f, sum0);
        const float inv1 = __fdividef(1.f, sum1);
        float cc[8][4];
#pragma unroll
        for (int tn = 0; tn < 8; tn++)
#pragma unroll
            for (int j = 0; j < 4; j++) cc[tn][j] = 0.f;
#pragma unroll
        for (int tl2 = 0; tl2 < 2; tl2++) {
            unsigned a[4];
            a[0] = h2u(plo[2 * tl2]);
            a[1] = h2u(phi[2 * tl2]);
            a[2] = h2u(plo[2 * tl2 + 1]);
            a[3] = h2u(phi[2 * tl2 + 1]);
#pragma unroll
            for (int tn = 0; tn < 8; tn++) {
                unsigned bb[2];
                bb[0] = *(const unsigned*)&Vs[(8 * tl2 + tig) * 72 + 8 * tn + g];
                bb[1] = *(const unsigned*)&Vs[(8 * tl2 + tig + 4) * 72 + 8 * tn + g];
                mma_f16(cc[tn], a, bb);
            }
        }
        const int r0 = chunkBase + mb + g, r1 = chunkBase + mb + 8 + g;
        if (r0 < NV) {
            const size_t row = (size_t)b * NV + r0;
#pragma unroll
            for (int tn = 0; tn < 8; tn++) {
                const int d0 = 8 * tn + 2 * tig;
                ctxh[row * 384 + h * 32 + (d0 >> 1)] =
                    __floats2half2_rn(cc[tn][0] * inv0, cc[tn][1] * inv0);
            }
        }
        if (r1 < NV) {
            const size_t row = (size_t)b * NV + r1;
#pragma unroll
            for (int tn = 0; tn < 8; tn++) {
                const int d0 = 8 * tn + 2 * tig;
                ctxh[row * 384 + h * 32 + (d0 >> 1)] =
                    __floats2half2_rn(cc[tn][2] * inv1, cc[tn][3] * inv1);
            }
        }
    }
}

// ---------------------------------------------------------------------------
// Output finalize: logits = b2 + 3 stripe partials; rel = 1/32.
// ---------------------------------------------------------------------------
__global__ void __launch_bounds__(256)
finalize_kernel(const float* __restrict__ part, const float* __restrict__ b2,
                float* __restrict__ out)
{
    const int idx = blockIdx.x * 256 + threadIdx.x;
    if (idx < MQ * 2) {
        const int o = idx & 1;
        out[idx] = b2[o] + part[idx] + part[(size_t)MQ * 2 + idx]
                 + part[(size_t)2 * MQ * 2 + idx];
    } else if (idx < MQ * 3) {
        out[idx] = 0.03125f;
    }
}

// ---------------------------------------------------------------------------
extern "C" void kernel_launch(void* const* d_in, const int* in_sizes, int n_in,
                              void* d_out, int out_size)
{
    const float* vis  = (const float*)d_in[0];
    const float* text = (const float*)d_in[1];
    const float* Wq = (const float*)d_in[2];
    const float* bq = (const float*)d_in[3];
    const float* Wk = (const float*)d_in[4];
    const float* bk = (const float*)d_in[5];
    const float* Wv = (const float*)d_in[6];
    const float* bv = (const float*)d_in[7];
    const float* W1 = (const float*)d_in[8];
    const float* b1 = (const float*)d_in[9];
    const float* W2 = (const float*)d_in[10];
    const float* b2 = (const float*)d_in[11];
    float* out = (float*)d_out;

    __half2 *qh, *kvh, *ctxh;
    float *partp, *bkv;
    uint2 *wkvF, *wqF, *w1F;
    cudaGetSymbolAddress((void**)&qh,    g_qh);
    cudaGetSymbolAddress((void**)&kvh,   g_kvh);
    cudaGetSymbolAddress((void**)&ctxh,  g_ctxh);
    cudaGetSymbolAddress((void**)&partp, g_part);
    cudaGetSymbolAddress((void**)&wkvF,  g_wkvF);
    cudaGetSymbolAddress((void**)&wqF,   g_wqF);
    cudaGetSymbolAddress((void**)&w1F,   g_w1F);
    cudaGetSymbolAddress((void**)&bkv,   g_bkv);

    pack_all_kernel<<<dim3(576, 4), 256>>>(Wk, Wv, Wq, W1, wkvF, wqF, w1F);
    cudaMemcpyAsync(bkv,      bk, CI * sizeof(float), cudaMemcpyDeviceToDevice);
    cudaMemcpyAsync(bkv + CI, bv, CI * sizeof(float), cudaMemcpyDeviceToDevice);

    // Combined K|V projection: [8192,512] @ [512,1536] -> fp16
    gemm_f16_kernel<false, false, false><<<dim3(NKV / 256, MKV / 128), 256>>>(
        text, nullptr, wkvF, bkv, kvh, nullptr, nullptr, MKV, NKV, CT);
    // Q projection: [50176,768] @ [768,768] -> fp16
    gemm_f16_kernel<false, false, false><<<dim3(CI / 256, MQ / 128), 256>>>(
        vis, nullptr, wqF, bq, qh, nullptr, nullptr, MQ, CI, CV);
    // Tensor attention -> normalized ctx fp16 (no residual read)
    attn_kernel<<<BATCH * NHEAD * 2, 128>>>(qh, kvh, ctxh);
    // MLP hidden GEMM: A = ctx + vis fused at load; gelu + head partials
    gemm_f16_kernel<true, true, true><<<dim3(CI / 256, MQ / 128), 256>>>(
        ctxh, vis, w1F, b1, nullptr, W2, partp, MQ, CI, CI);
    finalize_kernel<<<(MQ * 3 + 255) / 256, 256>>>(partp, b2, out);
}

// round 14
// speedup vs baseline: 1.0003x; 1.0003x over previous
#include <cuda_runtime.h>
#include <cuda_fp16.h>
#include <cstdint>
#include <math.h>

// Problem constants
#define BATCH 256
#define NV    196
#define LT    32
#define CV    768
#define CT    512
#define CI    768
#define NHEAD 12
#define DHEAD 64

#define MQ  (BATCH*NV)   // 50176
#define MKV (BATCH*LT)   // 8192
#define NKV 1536         // combined K|V projection width

// Scratch (allocation-free rule: __device__ globals) — fp16 intermediates
__device__ __half2 g_qh[(size_t)MQ * (CI/2)];
__device__ __half2 g_kvh[(size_t)MKV * (NKV/2)];
__device__ __half2 g_ctxh[(size_t)MQ * (CI/2)];
__device__ __half2 g_vish[(size_t)MQ * (CV/2)];
__device__ float   g_part[(size_t)3 * MQ * 2];
// fp16 weights pre-packed in mma-fragment order
__device__ uint2 g_wkvF[(size_t)(CT/16) * (NKV/8) * 32];
__device__ uint2 g_wqF[(size_t)(CV/16) * (CI/8) * 32];
__device__ uint2 g_w1F[(size_t)(CI/16) * (CI/8) * 32];
__device__ float g_bkv[NKV];

// ---------------------------------------------------------------------------
__device__ __forceinline__ void mma_f16(float* c, const unsigned* a, const unsigned* b) {
    asm volatile(
        "mma.sync.aligned.m16n8k16.row.col.f32.f16.f16.f32 "
        "{%0,%1,%2,%3}, {%4,%5,%6,%7}, {%8,%9}, {%0,%1,%2,%3};\n"
        : "+f"(c[0]), "+f"(c[1]), "+f"(c[2]), "+f"(c[3])
        : "r"(a[0]), "r"(a[1]), "r"(a[2]), "r"(a[3]), "r"(b[0]), "r"(b[1]));
}
__device__ __forceinline__ unsigned h2u(const __half2 h) { return *(const unsigned*)&h; }
__device__ __forceinline__ void ldmatrix_x4(unsigned* r, unsigned addr) {
    asm volatile("ldmatrix.sync.aligned.m8n8.x4.shared.b16 {%0,%1,%2,%3}, [%4];"
        : "=r"(r[0]), "=r"(r[1]), "=r"(r[2]), "=r"(r[3]) : "r"(addr));
}

// ---------------------------------------------------------------------------
// Fused weight pack: blockIdx.y selects {Wk->kv, Wv->kv(+off), Wq, W1}.
// ---------------------------------------------------------------------------
__global__ void __launch_bounds__(256)
pack_all_kernel(const float* __restrict__ Wk, const float* __restrict__ Wv,
                const float* __restrict__ Wq, const float* __restrict__ W1,
                uint2* __restrict__ wkvF, uint2* __restrict__ wqF,
                uint2* __restrict__ w1F)
{
    const int which = blockIdx.y;
    const float* W;
    uint2* out;
    int K, outNtiles, tnOff;
    switch (which) {
        case 0: W = Wk; out = wkvF; K = CT; outNtiles = NKV/8; tnOff = 0;    break;
        case 1: W = Wv; out = wkvF; K = CT; outNtiles = NKV/8; tnOff = CI/8; break;
        case 2: W = Wq; out = wqF;  K = CV; outNtiles = CI/8;  tnOff = 0;    break;
        default:W = W1; out = w1F;  K = CI; outNtiles = CI/8;  tnOff = 0;    break;
    }
    const int N = CI;
    const int idx = blockIdx.x * 256 + threadIdx.x;
    const int total = (K / 16) * (N / 8) * 32;
    if (idx >= total) return;
    const int lane = idx & 31;
    const int tile = idx >> 5;
    const int ntiles = N / 8;
    const int tn = tile % ntiles;
    const int tk = tile / ntiles;
    const int g = lane >> 2, tig = lane & 3;
    const int n = tn * 8 + g;
    const int k0 = tk * 16 + 2 * tig;
    const __half2 b0 = __floats2half2_rn(W[(size_t)k0 * N + n], W[(size_t)(k0 + 1) * N + n]);
    const __half2 b1 = __floats2half2_rn(W[(size_t)(k0 + 8) * N + n], W[(size_t)(k0 + 9) * N + n]);
    uint2 r;
    r.x = h2u(b0);
    r.y = h2u(b1);
    out[((size_t)tk * outNtiles + tnOff + tn) * 32 + lane] = r;
}

// ---------------------------------------------------------------------------
// FP16 mma.sync GEMM (R9/R11-proven structure). Block 128x256, 8 warps,
// warp 64x64. A single-buffer smem + register staging, fragments via
// ldmatrix.x4; B fragment-order from global, register double-buffered.
// STOREA: (fp32-A path) blockIdx.x==0 stripe also writes the converted fp16
//         A tile to vish (Q GEMM produces half(vis) as a byproduct).
// ADDVISH: (fp16-A path) A = ctx + vish via __hadd2 at STS (residual fold).
// ---------------------------------------------------------------------------
#define AS2_STRIDE 20

template <bool AHALF, bool MLPHEAD, bool STOREA, bool ADDVISH>
__global__ void __launch_bounds__(256)
gemm_f16_kernel(const void* __restrict__ Aptr, const uint2* __restrict__ Bf,
                const float* __restrict__ bias, __half2* __restrict__ Ch,
                __half2* __restrict__ vish,
                const float* __restrict__ W2, float* __restrict__ part,
                int M, int N, int K)
{
    __shared__ __half2 As[128 * AS2_STRIDE];
    __shared__ float red[4][128][2];   // only used when MLPHEAD

    const int tid = threadIdx.x;
    const int warp = tid >> 5, lane = tid & 31;
    const int g = lane >> 2, tig = lane & 3;
    const int wm = (warp >> 2) * 64;
    const int wnIdx = warp & 3;
    const int wn = wnIdx * 64;
    const int rowBase = blockIdx.y * 128;
    const int colBase = blockIdx.x * 256;
    const int Ntiles = N >> 3;
    const int tnBase = (colBase + wn) >> 3;

    const int lmRow = wm + (lane & 7) + ((lane >> 3) & 1) * 8;
    const int lmCol = (lane >> 4) * 4;
    const unsigned lmBase =
        (unsigned)__cvta_generic_to_shared(&As[lmRow * AS2_STRIDE + lmCol]);

    float acc[4][8][4];
#pragma unroll
    for (int mt = 0; mt < 4; mt++)
#pragma unroll
        for (int nt = 0; nt < 8; nt++)
#pragma unroll
            for (int r = 0; r < 4; r++) acc[mt][nt][r] = 0.f;

    const int KT = K >> 5;
    const int TKT = KT * 2;
    float4 ar[4];
    uint4 arh[2];
    uint4 vrh[2];

    auto ldg_a = [&](int kt) {
        if (AHALF) {
            const __half2* Ah = (const __half2*)Aptr;
#pragma unroll
            for (int i = 0; i < 2; i++) {
                const int f = tid + i * 256;
                const int r = f >> 2, c4 = (f & 3) * 4;
                arh[i] = *(const uint4*)(Ah + (size_t)(rowBase + r) * (K / 2) + kt * 16 + c4);
                if (ADDVISH)
                    vrh[i] = *(const uint4*)(vish + (size_t)(rowBase + r) * (K / 2) + kt * 16 + c4);
            }
        } else {
            const float* Af = (const float*)Aptr;
#pragma unroll
            for (int i = 0; i < 4; i++) {
                const int f = tid + i * 256;
                const int r = f >> 3, c4 = (f & 7) * 4;
                ar[i] = *(const float4*)(Af + (size_t)(rowBase + r) * K + kt * 32 + c4);
            }
        }
    };

    uint2 bfr[2][8];
    {   // preload B fragments for tk = 0
        const uint2* bp = Bf + (size_t)tnBase * 32 + lane;
#pragma unroll
        for (int nt = 0; nt < 8; nt++) bfr[0][nt] = bp[nt * 32];
    }
    ldg_a(0);

    for (int kt = 0; kt < KT; kt++) {
        if (kt) __syncthreads();
        if (AHALF) {
#pragma unroll
            for (int i = 0; i < 2; i++) {
                const int f = tid + i * 256;
                const int r = f >> 2, c4 = (f & 3) * 4;
                uint4 v = arh[i];
                if (ADDVISH) {
                    const unsigned* wu = (const unsigned*)&vrh[i];
                    unsigned* vu = (unsigned*)&v;
#pragma unroll
                    for (int j = 0; j < 4; j++) {
                        const __half2 s = __hadd2(*(const __half2*)&vu[j],
                                                  *(const __half2*)&wu[j]);
                        vu[j] = h2u(s);
                    }
                }
                *(uint4*)&As[r * AS2_STRIDE + c4] = v;
            }
        } else {
#pragma unroll
            for (int i = 0; i < 4; i++) {
                const int f = tid + i * 256;
                const int r = f >> 3, c2 = (f & 7) * 2;
                const __half2 h0 = __floats2half2_rn(ar[i].x, ar[i].y);
                const __half2 h1 = __floats2half2_rn(ar[i].z, ar[i].w);
                __half2* dst = &As[r * AS2_STRIDE + c2];
                dst[0] = h0; dst[1] = h1;
                if (STOREA && colBase == 0) {
                    uint2 sv; sv.x = h2u(h0); sv.y = h2u(h1);
                    *(uint2*)(vish + (size_t)(rowBase + r) * (K / 2) + kt * 16 + c2) = sv;
                }
            }
        }
        __syncthreads();

        if (kt + 1 < KT) ldg_a(kt + 1);

#pragma unroll
        for (int k16 = 0; k16 < 2; k16++) {
            const int tk = kt * 2 + k16;
            const int cur = tk & 1;
            if (tk + 1 < TKT) {
                const uint2* bp = Bf + ((size_t)(tk + 1) * Ntiles + tnBase) * 32 + lane;
#pragma unroll
                for (int nt = 0; nt < 8; nt++) bfr[cur ^ 1][nt] = bp[nt * 32];
            }
            unsigned a[4][4];
            const unsigned kOff = k16 * 8 * 4;
#pragma unroll
            for (int mt = 0; mt < 4; mt++)
                ldmatrix_x4(a[mt], lmBase + mt * 16 * AS2_STRIDE * 4 + kOff);
#pragma unroll
            for (int mt = 0; mt < 4; mt++)
#pragma unroll
                for (int nt = 0; nt < 8; nt++)
                    mma_f16(acc[mt][nt], a[mt], (const unsigned*)&bfr[cur][nt]);
        }
    }

    if (!MLPHEAD) {
        const int Nh = N >> 1;
#pragma unroll
        for (int mt = 0; mt < 4; mt++) {
            const int r0 = rowBase + wm + mt * 16 + g;
            const int r1 = r0 + 8;
#pragma unroll
            for (int nt = 0; nt < 8; nt++) {
                const int c = colBase + wn + nt * 8 + tig * 2;
                const float b0 = bias[c], b1 = bias[c + 1];
                Ch[(size_t)r0 * Nh + (c >> 1)] =
                    __floats2half2_rn(acc[mt][nt][0] + b0, acc[mt][nt][1] + b1);
                Ch[(size_t)r1 * Nh + (c >> 1)] =
                    __floats2half2_rn(acc[mt][nt][2] + b0, acc[mt][nt][3] + b1);
            }
        }
    } else {
#pragma unroll
        for (int mt = 0; mt < 4; mt++) {
            float h00 = 0.f, h01 = 0.f, h10 = 0.f, h11 = 0.f;
#pragma unroll
            for (int nt = 0; nt < 8; nt++) {
                const int c = colBase + wn + nt * 8 + tig * 2;
                const float b0 = bias[c], b1 = bias[c + 1];
                float v00 = acc[mt][nt][0] + b0, v01 = acc[mt][nt][1] + b1;
                float v10 = acc[mt][nt][2] + b0, v11 = acc[mt][nt][3] + b1;
                v00 = v00 / (1.f + __expf(-1.702f * v00));
                v01 = v01 / (1.f + __expf(-1.702f * v01));
                v10 = v10 / (1.f + __expf(-1.702f * v10));
                v11 = v11 / (1.f + __expf(-1.702f * v11));
                const float4 w4 = *(const float4*)(W2 + 2 * c);
                h00 += v00 * w4.x + v01 * w4.z;
                h01 += v00 * w4.y + v01 * w4.w;
                h10 += v10 * w4.x + v11 * w4.z;
                h11 += v10 * w4.y + v11 * w4.w;
            }
#pragma unroll
            for (int o = 1; o <= 2; o <<= 1) {
                h00 += __shfl_xor_sync(0xffffffff, h00, o);
                h01 += __shfl_xor_sync(0xffffffff, h01, o);
                h10 += __shfl_xor_sync(0xffffffff, h10, o);
                h11 += __shfl_xor_sync(0xffffffff, h11, o);
            }
            if (tig == 0) {
                const int rl = wm + mt * 16 + g;
                red[wnIdx][rl][0] = h00; red[wnIdx][rl][1] = h01;
                red[wnIdx][rl + 8][0] = h10; red[wnIdx][rl + 8][1] = h11;
            }
        }
        __syncthreads();
        const int rl = tid >> 1, o = tid & 1;
        const float s = red[0][rl][o] + red[1][rl][o] + red[2][rl][o] + red[3][rl][o];
        part[(size_t)blockIdx.x * MQ * 2 + (size_t)(rowBase + rl) * 2 + o] = s;
    }
}

// ---------------------------------------------------------------------------
// Tensor-core attention. TWO blocks per (b,h). Stores NORMALIZED ctx (fp16)
// only — the residual add lives in the MLP GEMM's A-loader (vish).
// ---------------------------------------------------------------------------
__global__ void __launch_bounds__(128)
attn_kernel(const __half2* __restrict__ qh, const __half2* __restrict__ kvh,
            __half2* __restrict__ ctxh)
{
    __shared__ __half2 Qs[112 * 36];
    __shared__ __half2 Ks[32 * 36];
    __shared__ __half2 Vs[16 * 72];

    const int bh = blockIdx.x >> 1;
    const int chunk = blockIdx.x & 1;
    const int b = bh / NHEAD;
    const int h = bh % NHEAD;
    const int tid = threadIdx.x;
    const int warp = tid >> 5, lane = tid & 31;
    const int g = lane >> 2, tig = lane & 3;

    const int chunkBase = chunk * 112;
    const int nRows = chunk ? (NV - 112) : 112;
    const int numTiles = chunk ? 6 : 7;

    for (int f = tid; f < nRows * 8; f += 128) {
        const int n = f >> 3, c = f & 7;
        *(uint4*)&Qs[n * 36 + c * 4] =
            *(const uint4*)(qh + ((size_t)b * NV + chunkBase + n) * 384 + h * 32 + c * 4);
    }
    const int padRows = numTiles * 16 - nRows;
    for (int f = tid; f < padRows * 36; f += 128) {
        Qs[nRows * 36 + f] = __half2(__ushort_as_half(0), __ushort_as_half(0));
    }
    for (int f = tid; f < 32 * 8; f += 128) {
        const int l = f >> 3, c = f & 7;
        *(uint4*)&Ks[l * 36 + c * 4] =
            *(const uint4*)(kvh + ((size_t)b * LT + l) * 768 + h * 32 + c * 4);
    }
    __half* Vsh = (__half*)Vs;
    for (int f = tid; f < 32 * 32; f += 128) {
        const int l = f >> 5, d2 = f & 31;
        const __half2 val = kvh[((size_t)b * LT + l) * 768 + 384 + h * 32 + d2];
        const int base = (l >> 1) * 144 + 4 * d2 + (l & 1);
        Vsh[base] = __low2half(val);
        Vsh[base + 2] = __high2half(val);
    }
    __syncthreads();

    for (int t = warp; t < numTiles; t += 4) {
        const int mb = t * 16;
        float sc[4][4];
#pragma unroll
        for (int tl = 0; tl < 4; tl++)
#pragma unroll
            for (int j = 0; j < 4; j++) sc[tl][j] = 0.f;
#pragma unroll
        for (int td = 0; td < 4; td++) {
            unsigned a[4];
            a[0] = *(const unsigned*)&Qs[(mb + g) * 36 + 8 * td + tig];
            a[1] = *(const unsigned*)&Qs[(mb + 8 + g) * 36 + 8 * td + tig];
            a[2] = *(const unsigned*)&Qs[(mb + g) * 36 + 8 * td + tig + 4];
            a[3] = *(const unsigned*)&Qs[(mb + 8 + g) * 36 + 8 * td + tig + 4];
#pragma unroll
            for (int tl = 0; tl < 4; tl++) {
                unsigned bb[2];
                bb[0] = *(const unsigned*)&Ks[(8 * tl + g) * 36 + 8 * td + tig];
                bb[1] = *(const unsigned*)&Ks[(8 * tl + g) * 36 + 8 * td + tig + 4];
                mma_f16(sc[tl], a, bb);
            }
        }
        float mx0 = -1e30f, mx1 = -1e30f;
#pragma unroll
        for (int tl = 0; tl < 4; tl++) {
#pragma unroll
            for (int j = 0; j < 4; j++) sc[tl][j] *= 0.125f;
            mx0 = fmaxf(mx0, fmaxf(sc[tl][0], sc[tl][1]));
            mx1 = fmaxf(mx1, fmaxf(sc[tl][2], sc[tl][3]));
        }
        mx0 = fmaxf(mx0, __shfl_xor_sync(0xffffffff, mx0, 1));
        mx0 = fmaxf(mx0, __shfl_xor_sync(0xffffffff, mx0, 2));
        mx1 = fmaxf(mx1, __shfl_xor_sync(0xffffffff, mx1, 1));
        mx1 = fmaxf(mx1, __shfl_xor_sync(0xffffffff, mx1, 2));
        __half2 plo[4], phi[4];
        float sum0 = 0.f, sum1 = 0.f;
#pragma unroll
        for (int tl = 0; tl < 4; tl++) {
            const __half2 e0 = h2exp(__floats2half2_rn(sc[tl][0] - mx0, sc[tl][1] - mx0));
            const __half2 e1 = h2exp(__floats2half2_rn(sc[tl][2] - mx1, sc[tl][3] - mx1));
            plo[tl] = e0; phi[tl] = e1;
            const float2 f0 = __half22float2(e0);
            const float2 f1 = __half22float2(e1);
            sum0 += f0.x + f0.y;
            sum1 += f1.x + f1.y;
        }
        sum0 += __shfl_xor_sync(0xffffffff, sum0, 1);
        sum0 += __shfl_xor_sync(0xffffffff, sum0, 2);
        sum1 += __shfl_xor_sync(0xffffffff, sum1, 1);
        sum1 += __shfl_xor_sync(0xffffffff, sum1, 2);
        const float inv0 = __fdividef(1.f, sum0);
        const float inv1 = __fdividef(1.f, sum1);
        float cc[8][4];
#pragma unroll
        for (int tn = 0; tn < 8; tn++)
#pragma unroll
            for (int j = 0; j < 4; j++) cc[tn][j] = 0.f;
#pragma unroll
        for (int tl2 = 0; tl2 < 2; tl2++) {
            unsigned a[4];
            a[0] = h2u(plo[2 * tl2]);
            a[1] = h2u(phi[2 * tl2]);
            a[2] = h2u(plo[2 * tl2 + 1]);
            a[3] = h2u(phi[2 * tl2 + 1]);
#pragma unroll
            for (int tn = 0; tn < 8; tn++) {
                unsigned bb[2];
                bb[0] = *(const unsigned*)&Vs[(8 * tl2 + tig) * 72 + 8 * tn + g];
                bb[1] = *(const unsigned*)&Vs[(8 * tl2 + tig + 4) * 72 + 8 * tn + g];
                mma_f16(cc[tn], a, bb);
            }
        }
        const int r0 = chunkBase + mb + g, r1 = chunkBase + mb + 8 + g;
        if (r0 < NV) {
            const size_t row = (size_t)b * NV + r0;
#pragma unroll
            for (int tn = 0; tn < 8; tn++) {
                const int d0 = 8 * tn + 2 * tig;
                ctxh[row * 384 + h * 32 + (d0 >> 1)] =
                    __floats2half2_rn(cc[tn][0] * inv0, cc[tn][1] * inv0);
            }
        }
        if (r1 < NV) {
            const size_t row = (size_t)b * NV + r1;
#pragma unroll
            for (int tn = 0; tn < 8; tn++) {
                const int d0 = 8 * tn + 2 * tig;
                ctxh[row * 384 + h * 32 + (d0 >> 1)] =
                    __floats2half2_rn(cc[tn][2] * inv1, cc[tn][3] * inv1);
            }
        }
    }
}

// ---------------------------------------------------------------------------
// Output finalize: logits = b2 + 3 stripe partials; rel = 1/32.
// ---------------------------------------------------------------------------
__global__ void __launch_bounds__(256)
finalize_kernel(const float* __restrict__ part, const float* __restrict__ b2,
                float* __restrict__ out)
{
    const int idx = blockIdx.x * 256 + threadIdx.x;
    if (idx < MQ * 2) {
        const int o = idx & 1;
        out[idx] = b2[o] + part[idx] + part[(size_t)MQ * 2 + idx]
                 + part[(size_t)2 * MQ * 2 + idx];
    } else if (idx < MQ * 3) {
        out[idx] = 0.03125f;
    }
}

// ---------------------------------------------------------------------------
extern "C" void kernel_launch(void* const* d_in, const int* in_sizes, int n_in,
                              void* d_out, int out_size)
{
    const float* vis  = (const float*)d_in[0];
    const float* text = (const float*)d_in[1];
    const float* Wq = (const float*)d_in[2];
    const float* bq = (const float*)d_in[3];
    const float* Wk = (const float*)d_in[4];
    const float* bk = (const float*)d_in[5];
    const float* Wv = (const float*)d_in[6];
    const float* bv = (const float*)d_in[7];
    const float* W1 = (const float*)d_in[8];
    const float* b1 = (const float*)d_in[9];
    const float* W2 = (const float*)d_in[10];
    const float* b2 = (const float*)d_in[11];
    float* out = (float*)d_out;

    __half2 *qh, *kvh, *ctxh, *vish;
    float *partp, *bkv;
    uint2 *wkvF, *wqF, *w1F;
    cudaGetSymbolAddress((void**)&qh,    g_qh);
    cudaGetSymbolAddress((void**)&kvh,   g_kvh);
    cudaGetSymbolAddress((void**)&ctxh,  g_ctxh);
    cudaGetSymbolAddress((void**)&vish,  g_vish);
    cudaGetSymbolAddress((void**)&partp, g_part);
    cudaGetSymbolAddress((void**)&wkvF,  g_wkvF);
    cudaGetSymbolAddress((void**)&wqF,   g_wqF);
    cudaGetSymbolAddress((void**)&w1F,   g_w1F);
    cudaGetSymbolAddress((void**)&bkv,   g_bkv);

    pack_all_kernel<<<dim3(576, 4), 256>>>(Wk, Wv, Wq, W1, wkvF, wqF, w1F);
    cudaMemcpyAsync(bkv,      bk, CI * sizeof(float), cudaMemcpyDeviceToDevice);
    cudaMemcpyAsync(bkv + CI, bv, CI * sizeof(float), cudaMemcpyDeviceToDevice);

    // Combined K|V projection: [8192,512] @ [512,1536] -> fp16
    gemm_f16_kernel<false, false, false, false><<<dim3(NKV / 256, MKV / 128), 256>>>(
        text, wkvF, bkv, kvh, nullptr, nullptr, nullptr, MKV, NKV, CT);
    // Q projection: [50176,768] @ [768,768] -> fp16; stripe 0 also emits vish
    gemm_f16_kernel<false, false, true, false><<<dim3(CI / 256, MQ / 128), 256>>>(
        vis, wqF, bq, qh, vish, nullptr, nullptr, MQ, CI, CV);
    // Tensor attention -> normalized ctx fp16 (no residual read)
    attn_kernel<<<BATCH * NHEAD * 2, 128>>>(qh, kvh, ctxh);
    // MLP hidden GEMM: A = ctx + vish (__hadd2) at STS; gelu + head partials
    gemm_f16_kernel<true, true, false, true><<<dim3(CI / 256, MQ / 128), 256>>>(
        ctxh, w1F, b1, nullptr, vish, W2, partp, MQ, CI, CI);
    finalize_kernel<<<(MQ * 3 + 255) / 256, 256>>>(partp, b2, out);
}

// round 15
// speedup vs baseline: 1.0608x; 1.0605x over previous
#include <cuda_runtime.h>
#include <cuda_fp16.h>
#include <cstdint>
#include <math.h>

// Problem constants
#define BATCH 256
#define NV    196
#define LT    32
#define CV    768
#define CT    512
#define CI    768
#define NHEAD 12
#define DHEAD 64

#define MQ  (BATCH*NV)   // 50176
#define MKV (BATCH*LT)   // 8192
#define NKV 1536         // combined K|V projection width

// Scratch (allocation-free rule: __device__ globals) — fp16 intermediates
__device__ __half2 g_qh[(size_t)MQ * (CI/2)];
__device__ __half2 g_kvh[(size_t)MKV * (NKV/2)];
__device__ __half2 g_fusedh[(size_t)MQ * (CI/2)];
__device__ float   g_part[(size_t)3 * MQ * 2];
// fp16 weights pre-packed in mma-fragment order
__device__ uint2 g_wkvF[(size_t)(CT/16) * (NKV/8) * 32];
__device__ uint2 g_wqF[(size_t)(CV/16) * (CI/8) * 32];
__device__ uint2 g_w1F[(size_t)(CI/16) * (CI/8) * 32];
__device__ float g_bkv[NKV];

// ---------------------------------------------------------------------------
__device__ __forceinline__ void mma_f16(float* c, const unsigned* a, const unsigned* b) {
    asm volatile(
        "mma.sync.aligned.m16n8k16.row.col.f32.f16.f16.f32 "
        "{%0,%1,%2,%3}, {%4,%5,%6,%7}, {%8,%9}, {%0,%1,%2,%3};\n"
        : "+f"(c[0]), "+f"(c[1]), "+f"(c[2]), "+f"(c[3])
        : "r"(a[0]), "r"(a[1]), "r"(a[2]), "r"(a[3]), "r"(b[0]), "r"(b[1]));
}
__device__ __forceinline__ unsigned h2u(const __half2 h) { return *(const unsigned*)&h; }
__device__ __forceinline__ void ldmatrix_x4(unsigned* r, unsigned addr) {
    asm volatile("ldmatrix.sync.aligned.m8n8.x4.shared.b16 {%0,%1,%2,%3}, [%4];"
        : "=r"(r[0]), "=r"(r[1]), "=r"(r[2]), "=r"(r[3]) : "r"(addr));
}

// ---------------------------------------------------------------------------
// Fused weight pack: blockIdx.y selects {Wk->kv, Wv->kv(+off), Wq, W1}.
// ---------------------------------------------------------------------------
__global__ void __launch_bounds__(256)
pack_all_kernel(const float* __restrict__ Wk, const float* __restrict__ Wv,
                const float* __restrict__ Wq, const float* __restrict__ W1,
                uint2* __restrict__ wkvF, uint2* __restrict__ wqF,
                uint2* __restrict__ w1F)
{
    const int which = blockIdx.y;
    const float* W;
    uint2* out;
    int K, outNtiles, tnOff;
    switch (which) {
        case 0: W = Wk; out = wkvF; K = CT; outNtiles = NKV/8; tnOff = 0;    break;
        case 1: W = Wv; out = wkvF; K = CT; outNtiles = NKV/8; tnOff = CI/8; break;
        case 2: W = Wq; out = wqF;  K = CV; outNtiles = CI/8;  tnOff = 0;    break;
        default:W = W1; out = w1F;  K = CI; outNtiles = CI/8;  tnOff = 0;    break;
    }
    const int N = CI;
    const int idx = blockIdx.x * 256 + threadIdx.x;
    const int total = (K / 16) * (N / 8) * 32;
    if (idx >= total) return;
    const int lane = idx & 31;
    const int tile = idx >> 5;
    const int ntiles = N / 8;
    const int tn = tile % ntiles;
    const int tk = tile / ntiles;
    const int g = lane >> 2, tig = lane & 3;
    const int n = tn * 8 + g;
    const int k0 = tk * 16 + 2 * tig;
    const __half2 b0 = __floats2half2_rn(W[(size_t)k0 * N + n], W[(size_t)(k0 + 1) * N + n]);
    const __half2 b1 = __floats2half2_rn(W[(size_t)(k0 + 8) * N + n], W[(size_t)(k0 + 9) * N + n]);
    uint2 r;
    r.x = h2u(b0);
    r.y = h2u(b1);
    out[((size_t)tk * outNtiles + tnOff + tn) * 32 + lane] = r;
}

// ---------------------------------------------------------------------------
// FP16 mma.sync GEMM (R9/R11-proven structure — UNTOUCHED). Block 128x256,
// 8 warps, warp 64x64. A single-buffer smem + register staging, fragments via
// ldmatrix.x4; B fragment-order from global, register double-buffered.
// ---------------------------------------------------------------------------
#define AS2_STRIDE 20

template <bool AHALF, bool MLPHEAD>
__global__ void __launch_bounds__(256)
gemm_f16_kernel(const void* __restrict__ Aptr, const uint2* __restrict__ Bf,
                const float* __restrict__ bias, __half2* __restrict__ Ch,
                const float* __restrict__ W2, float* __restrict__ part,
                int M, int N, int K)
{
    __shared__ __half2 As[128 * AS2_STRIDE];
    __shared__ float red[4][128][2];   // only used when MLPHEAD

    const int tid = threadIdx.x;
    const int warp = tid >> 5, lane = tid & 31;
    const int g = lane >> 2, tig = lane & 3;
    const int wm = (warp >> 2) * 64;
    const int wnIdx = warp & 3;
    const int wn = wnIdx * 64;
    const int rowBase = blockIdx.y * 128;
    const int colBase = blockIdx.x * 256;
    const int Ntiles = N >> 3;
    const int tnBase = (colBase + wn) >> 3;

    const int lmRow = wm + (lane & 7) + ((lane >> 3) & 1) * 8;
    const int lmCol = (lane >> 4) * 4;
    const unsigned lmBase =
        (unsigned)__cvta_generic_to_shared(&As[lmRow * AS2_STRIDE + lmCol]);

    float acc[4][8][4];
#pragma unroll
    for (int mt = 0; mt < 4; mt++)
#pragma unroll
        for (int nt = 0; nt < 8; nt++)
#pragma unroll
            for (int r = 0; r < 4; r++) acc[mt][nt][r] = 0.f;

    const int KT = K >> 5;
    const int TKT = KT * 2;
    float4 ar[4];
    uint4 arh[2];

    auto ldg_a = [&](int kt) {
        if (AHALF) {
            const __half2* Ah = (const __half2*)Aptr;
#pragma unroll
            for (int i = 0; i < 2; i++) {
                const int f = tid + i * 256;
                const int r = f >> 2, c4 = (f & 3) * 4;
                arh[i] = *(const uint4*)(Ah + (size_t)(rowBase + r) * (K / 2) + kt * 16 + c4);
            }
        } else {
            const float* Af = (const float*)Aptr;
#pragma unroll
            for (int i = 0; i < 4; i++) {
                const int f = tid + i * 256;
                const int r = f >> 3, c4 = (f & 7) * 4;
                ar[i] = *(const float4*)(Af + (size_t)(rowBase + r) * K + kt * 32 + c4);
            }
        }
    };

    uint2 bfr[2][8];
    {   // preload B fragments for tk = 0
        const uint2* bp = Bf + (size_t)tnBase * 32 + lane;
#pragma unroll
        for (int nt = 0; nt < 8; nt++) bfr[0][nt] = bp[nt * 32];
    }
    ldg_a(0);

    for (int kt = 0; kt < KT; kt++) {
        if (kt) __syncthreads();
        if (AHALF) {
#pragma unroll
            for (int i = 0; i < 2; i++) {
                const int f = tid + i * 256;
                const int r = f >> 2, c4 = (f & 3) * 4;
                *(uint4*)&As[r * AS2_STRIDE + c4] = arh[i];
            }
        } else {
#pragma unroll
            for (int i = 0; i < 4; i++) {
                const int f = tid + i * 256;
                const int r = f >> 3, c2 = (f & 7) * 2;
                const __half2 h0 = __floats2half2_rn(ar[i].x, ar[i].y);
                const __half2 h1 = __floats2half2_rn(ar[i].z, ar[i].w);
                __half2* dst = &As[r * AS2_STRIDE + c2];
                dst[0] = h0; dst[1] = h1;
            }
        }
        __syncthreads();

        if (kt + 1 < KT) ldg_a(kt + 1);

#pragma unroll
        for (int k16 = 0; k16 < 2; k16++) {
            const int tk = kt * 2 + k16;
            const int cur = tk & 1;
            if (tk + 1 < TKT) {
                const uint2* bp = Bf + ((size_t)(tk + 1) * Ntiles + tnBase) * 32 + lane;
#pragma unroll
                for (int nt = 0; nt < 8; nt++) bfr[cur ^ 1][nt] = bp[nt * 32];
            }
            unsigned a[4][4];
            const unsigned kOff = k16 * 8 * 4;
#pragma unroll
            for (int mt = 0; mt < 4; mt++)
                ldmatrix_x4(a[mt], lmBase + mt * 16 * AS2_STRIDE * 4 + kOff);
#pragma unroll
            for (int mt = 0; mt < 4; mt++)
#pragma unroll
                for (int nt = 0; nt < 8; nt++)
                    mma_f16(acc[mt][nt], a[mt], (const unsigned*)&bfr[cur][nt]);
        }
    }

    if (!MLPHEAD) {
        const int Nh = N >> 1;
#pragma unroll
        for (int mt = 0; mt < 4; mt++) {
            const int r0 = rowBase + wm + mt * 16 + g;
            const int r1 = r0 + 8;
#pragma unroll
            for (int nt = 0; nt < 8; nt++) {
                const int c = colBase + wn + nt * 8 + tig * 2;
                const float b0 = bias[c], b1 = bias[c + 1];
                Ch[(size_t)r0 * Nh + (c >> 1)] =
                    __floats2half2_rn(acc[mt][nt][0] + b0, acc[mt][nt][1] + b1);
                Ch[(size_t)r1 * Nh + (c >> 1)] =
                    __floats2half2_rn(acc[mt][nt][2] + b0, acc[mt][nt][3] + b1);
            }
        }
    } else {
#pragma unroll
        for (int mt = 0; mt < 4; mt++) {
            float h00 = 0.f, h01 = 0.f, h10 = 0.f, h11 = 0.f;
#pragma unroll
            for (int nt = 0; nt < 8; nt++) {
                const int c = colBase + wn + nt * 8 + tig * 2;
                const float b0 = bias[c], b1 = bias[c + 1];
                float v00 = acc[mt][nt][0] + b0, v01 = acc[mt][nt][1] + b1;
                float v10 = acc[mt][nt][2] + b0, v11 = acc[mt][nt][3] + b1;
                v00 = v00 / (1.f + __expf(-1.702f * v00));
                v01 = v01 / (1.f + __expf(-1.702f * v01));
                v10 = v10 / (1.f + __expf(-1.702f * v10));
                v11 = v11 / (1.f + __expf(-1.702f * v11));
                const float4 w4 = *(const float4*)(W2 + 2 * c);
                h00 += v00 * w4.x + v01 * w4.z;
                h01 += v00 * w4.y + v01 * w4.w;
                h10 += v10 * w4.x + v11 * w4.z;
                h11 += v10 * w4.y + v11 * w4.w;
            }
#pragma unroll
            for (int o = 1; o <= 2; o <<= 1) {
                h00 += __shfl_xor_sync(0xffffffff, h00, o);
                h01 += __shfl_xor_sync(0xffffffff, h01, o);
                h10 += __shfl_xor_sync(0xffffffff, h10, o);
                h11 += __shfl_xor_sync(0xffffffff, h11, o);
            }
            if (tig == 0) {
                const int rl = wm + mt * 16 + g;
                red[wnIdx][rl][0] = h00; red[wnIdx][rl][1] = h01;
                red[wnIdx][rl + 8][0] = h10; red[wnIdx][rl + 8][1] = h11;
            }
        }
        __syncthreads();
        const int rl = tid >> 1, o = tid & 1;
        const float s = red[0][rl][o] + red[1][rl][o] + red[2][rl][o] + red[3][rl][o];
        part[(size_t)blockIdx.x * MQ * 2 + (size_t)(rowBase + rl) * 2 + o] = s;
    }
}

// ---------------------------------------------------------------------------
// Tensor-core attention + residual. TWO blocks per (b,h) (R12 layout).
// CHANGE vs R12: vis staged through smem (coalesced float4 loads, converted
// once to half2); epilogue adds from smem (__hadd2) instead of scattered
// per-thread global float2 loads. Writes fusedh. ~41 KB static smem.
// ---------------------------------------------------------------------------
__global__ void __launch_bounds__(128)
attn_kernel(const __half2* __restrict__ qh, const __half2* __restrict__ kvh,
            const float* __restrict__ vis, __half2* __restrict__ fusedh)
{
    __shared__ __half2 Qs[112 * 36];
    __shared__ __half2 Ks[32 * 36];
    __shared__ __half2 Vs[16 * 72];
    __shared__ __half2 VisS[112 * 36];

    const int bh = blockIdx.x >> 1;
    const int chunk = blockIdx.x & 1;
    const int b = bh / NHEAD;
    const int h = bh % NHEAD;
    const int tid = threadIdx.x;
    const int warp = tid >> 5, lane = tid & 31;
    const int g = lane >> 2, tig = lane & 3;

    const int chunkBase = chunk * 112;
    const int nRows = chunk ? (NV - 112) : 112;
    const int numTiles = chunk ? 6 : 7;

    // Q rows for this chunk
    for (int f = tid; f < nRows * 8; f += 128) {
        const int n = f >> 3, c = f & 7;
        *(uint4*)&Qs[n * 36 + c * 4] =
            *(const uint4*)(qh + ((size_t)b * NV + chunkBase + n) * 384 + h * 32 + c * 4);
    }
    const int padRows = numTiles * 16 - nRows;
    for (int f = tid; f < padRows * 36; f += 128) {
        Qs[nRows * 36 + f] = __half2(__ushort_as_half(0), __ushort_as_half(0));
    }
    // vis slice: nRows x 64 floats, coalesced float4 loads -> half2 smem
    for (int f = tid; f < nRows * 16; f += 128) {
        const int n = f >> 4, c = f & 15;    // c: float4 index 0..15
        const float4 v = *(const float4*)(vis +
            ((size_t)b * NV + chunkBase + n) * CV + h * 64 + c * 4);
        __half2* dst = &VisS[n * 36 + c * 2];
        dst[0] = __floats2half2_rn(v.x, v.y);
        dst[1] = __floats2half2_rn(v.z, v.w);
    }
    // K
    for (int f = tid; f < 32 * 8; f += 128) {
        const int l = f >> 3, c = f & 7;
        *(uint4*)&Ks[l * 36 + c * 4] =
            *(const uint4*)(kvh + ((size_t)b * LT + l) * 768 + h * 32 + c * 4);
    }
    // V repack to half2-over-l
    __half* Vsh = (__half*)Vs;
    for (int f = tid; f < 32 * 32; f += 128) {
        const int l = f >> 5, d2 = f & 31;
        const __half2 val = kvh[((size_t)b * LT + l) * 768 + 384 + h * 32 + d2];
        const int base = (l >> 1) * 144 + 4 * d2 + (l & 1);
        Vsh[base] = __low2half(val);
        Vsh[base + 2] = __high2half(val);
    }
    __syncthreads();

    for (int t = warp; t < numTiles; t += 4) {
        const int mb = t * 16;
        float sc[4][4];
#pragma unroll
        for (int tl = 0; tl < 4; tl++)
#pragma unroll
            for (int j = 0; j < 4; j++) sc[tl][j] = 0.f;
#pragma unroll
        for (int td = 0; td < 4; td++) {
            unsigned a[4];
            a[0] = *(const unsigned*)&Qs[(mb + g) * 36 + 8 * td + tig];
            a[1] = *(const unsigned*)&Qs[(mb + 8 + g) * 36 + 8 * td + tig];
            a[2] = *(const unsigned*)&Qs[(mb + g) * 36 + 8 * td + tig + 4];
            a[3] = *(const unsigned*)&Qs[(mb + 8 + g) * 36 + 8 * td + tig + 4];
#pragma unroll
            for (int tl = 0; tl < 4; tl++) {
                unsigned bb[2];
                bb[0] = *(const unsigned*)&Ks[(8 * tl + g) * 36 + 8 * td + tig];
                bb[1] = *(const unsigned*)&Ks[(8 * tl + g) * 36 + 8 * td + tig + 4];
                mma_f16(sc[tl], a, bb);
            }
        }
        float mx0 = -1e30f, mx1 = -1e30f;
#pragma unroll
        for (int tl = 0; tl < 4; tl++) {
#pragma unroll
            for (int j = 0; j < 4; j++) sc[tl][j] *= 0.125f;
            mx0 = fmaxf(mx0, fmaxf(sc[tl][0], sc[tl][1]));
            mx1 = fmaxf(mx1, fmaxf(sc[tl][2], sc[tl][3]));
        }
        mx0 = fmaxf(mx0, __shfl_xor_sync(0xffffffff, mx0, 1));
        mx0 = fmaxf(mx0, __shfl_xor_sync(0xffffffff, mx0, 2));
        mx1 = fmaxf(mx1, __shfl_xor_sync(0xffffffff, mx1, 1));
        mx1 = fmaxf(mx1, __shfl_xor_sync(0xffffffff, mx1, 2));
        __half2 plo[4], phi[4];
        float sum0 = 0.f, sum1 = 0.f;
#pragma unroll
        for (int tl = 0; tl < 4; tl++) {
            const __half2 e0 = h2exp(__floats2half2_rn(sc[tl][0] - mx0, sc[tl][1] - mx0));
            const __half2 e1 = h2exp(__floats2half2_rn(sc[tl][2] - mx1, sc[tl][3] - mx1));
            plo[tl] = e0; phi[tl] = e1;
            const float2 f0 = __half22float2(e0);
            const float2 f1 = __half22float2(e1);
            sum0 += f0.x + f0.y;
            sum1 += f1.x + f1.y;
        }
        sum0 += __shfl_xor_sync(0xffffffff, sum0, 1);
        sum0 += __shfl_xor_sync(0xffffffff, sum0, 2);
        sum1 += __shfl_xor_sync(0xffffffff, sum1, 1);
        sum1 += __shfl_xor_sync(0xffffffff, sum1, 2);
        const float inv0 = __fdividef(1.f, sum0);
        const float inv1 = __fdividef(1.f, sum1);
        float cc[8][4];
#pragma unroll
        for (int tn = 0; tn < 8; tn++)
#pragma unroll
            for (int j = 0; j < 4; j++) cc[tn][j] = 0.f;
#pragma unroll
        for (int tl2 = 0; tl2 < 2; tl2++) {
            unsigned a[4];
            a[0] = h2u(plo[2 * tl2]);
            a[1] = h2u(phi[2 * tl2]);
            a[2] = h2u(plo[2 * tl2 + 1]);
            a[3] = h2u(phi[2 * tl2 + 1]);
#pragma unroll
            for (int tn = 0; tn < 8; tn++) {
                unsigned bb[2];
                bb[0] = *(const unsigned*)&Vs[(8 * tl2 + tig) * 72 + 8 * tn + g];
                bb[1] = *(const unsigned*)&Vs[(8 * tl2 + tig + 4) * 72 + 8 * tn + g];
                mma_f16(cc[tn], a, bb);
            }
        }
        const int r0 = chunkBase + mb + g, r1 = chunkBase + mb + 8 + g;
        if (r0 < NV) {
            const size_t row = (size_t)b * NV + r0;
            const int rl = mb + g;
#pragma unroll
            for (int tn = 0; tn < 8; tn++) {
                const int c2 = 4 * tn + tig;   // half2 index within the 32
                const __half2 hv = __floats2half2_rn(cc[tn][0] * inv0, cc[tn][1] * inv0);
                fusedh[row * 384 + h * 32 + c2] = __hadd2(hv, VisS[rl * 36 + c2]);
            }
        }
        if (r1 < NV) {
            const size_t row = (size_t)b * NV + r1;
            const int rl = mb + 8 + g;
#pragma unroll
            for (int tn = 0; tn < 8; tn++) {
                const int c2 = 4 * tn + tig;
                const __half2 hv = __floats2half2_rn(cc[tn][2] * inv1, cc[tn][3] * inv1);
                fusedh[row * 384 + h * 32 + c2] = __hadd2(hv, VisS[rl * 36 + c2]);
            }
        }
    }
}

// ---------------------------------------------------------------------------
// Output finalize: logits = b2 + 3 stripe partials; rel = 1/32.
// ---------------------------------------------------------------------------
__global__ void __launch_bounds__(256)
finalize_kernel(const float* __restrict__ part, const float* __restrict__ b2,
                float* __restrict__ out)
{
    const int idx = blockIdx.x * 256 + threadIdx.x;
    if (idx < MQ * 2) {
        const int o = idx & 1;
        out[idx] = b2[o] + part[idx] + part[(size_t)MQ * 2 + idx]
                 + part[(size_t)2 * MQ * 2 + idx];
    } else if (idx < MQ * 3) {
        out[idx] = 0.03125f;
    }
}

// ---------------------------------------------------------------------------
extern "C" void kernel_launch(void* const* d_in, const int* in_sizes, int n_in,
                              void* d_out, int out_size)
{
    const float* vis  = (const float*)d_in[0];
    const float* text = (const float*)d_in[1];
    const float* Wq = (const float*)d_in[2];
    const float* bq = (const float*)d_in[3];
    const float* Wk = (const float*)d_in[4];
    const float* bk = (const float*)d_in[5];
    const float* Wv = (const float*)d_in[6];
    const float* bv = (const float*)d_in[7];
    const float* W1 = (const float*)d_in[8];
    const float* b1 = (const float*)d_in[9];
    const float* W2 = (const float*)d_in[10];
    const float* b2 = (const float*)d_in[11];
    float* out = (float*)d_out;

    __half2 *qh, *kvh, *fusedh;
    float *partp, *bkv;
    uint2 *wkvF, *wqF, *w1F;
    cudaGetSymbolAddress((void**)&qh,     g_qh);
    cudaGetSymbolAddress((void**)&kvh,    g_kvh);
    cudaGetSymbolAddress((void**)&fusedh, g_fusedh);
    cudaGetSymbolAddress((void**)&partp,  g_part);
    cudaGetSymbolAddress((void**)&wkvF,   g_wkvF);
    cudaGetSymbolAddress((void**)&wqF,    g_wqF);
    cudaGetSymbolAddress((void**)&w1F,    g_w1F);
    cudaGetSymbolAddress((void**)&bkv,    g_bkv);

    pack_all_kernel<<<dim3(576, 4), 256>>>(Wk, Wv, Wq, W1, wkvF, wqF, w1F);
    cudaMemcpyAsync(bkv,      bk, CI * sizeof(float), cudaMemcpyDeviceToDevice);
    cudaMemcpyAsync(bkv + CI, bv, CI * sizeof(float), cudaMemcpyDeviceToDevice);

    gemm_f16_kernel<false, false><<<dim3(NKV / 256, MKV / 128), 256>>>(
        text, wkvF, bkv, kvh, nullptr, nullptr, MKV, NKV, CT);
    gemm_f16_kernel<false, false><<<dim3(CI / 256, MQ / 128), 256>>>(
        vis, wqF, bq, qh, nullptr, nullptr, MQ, CI, CV);
    attn_kernel<<<BATCH * NHEAD * 2, 128>>>(qh, kvh, vis, fusedh);
    gemm_f16_kernel<true, true><<<dim3(CI / 256, MQ / 128), 256>>>(
        fusedh, w1F, b1, nullptr, W2, partp, MQ, CI, CI);
    finalize_kernel<<<(MQ * 3 + 255) / 256, 256>>>(partp, b2, out);
}

// round 16
// speedup vs baseline: 1.0901x; 1.0276x over previous
#include <cuda_runtime.h>
#include <cuda_fp16.h>
#include <cstdint>
#include <math.h>

// Problem constants
#define BATCH 256
#define NV    196
#define LT    32
#define CV    768
#define CT    512
#define CI    768
#define NHEAD 12
#define DHEAD 64

#define MQ  (BATCH*NV)   // 50176
#define MKV (BATCH*LT)   // 8192
#define NKV 1536         // combined K|V projection width

// Scratch (allocation-free rule: __device__ globals) — fp16 intermediates
__device__ __half2 g_qh[(size_t)MQ * (CI/2)];
__device__ __half2 g_kvh[(size_t)MKV * (NKV/2)];
__device__ __half2 g_fusedh[(size_t)MQ * (CI/2)];
__device__ float   g_part[(size_t)3 * MQ * 2];
// fp16 weights pre-packed in mma-fragment order
__device__ uint2 g_wkvF[(size_t)(CT/16) * (NKV/8) * 32];
__device__ uint2 g_wqF[(size_t)(CV/16) * (CI/8) * 32];
__device__ uint2 g_w1F[(size_t)(CI/16) * (CI/8) * 32];
__device__ float g_bkv[NKV];

// ---------------------------------------------------------------------------
__device__ __forceinline__ void mma_f16(float* c, const unsigned* a, const unsigned* b) {
    asm volatile(
        "mma.sync.aligned.m16n8k16.row.col.f32.f16.f16.f32 "
        "{%0,%1,%2,%3}, {%4,%5,%6,%7}, {%8,%9}, {%0,%1,%2,%3};\n"
        : "+f"(c[0]), "+f"(c[1]), "+f"(c[2]), "+f"(c[3])
        : "r"(a[0]), "r"(a[1]), "r"(a[2]), "r"(a[3]), "r"(b[0]), "r"(b[1]));
}
__device__ __forceinline__ unsigned h2u(const __half2 h) { return *(const unsigned*)&h; }
__device__ __forceinline__ void ldmatrix_x4(unsigned* r, unsigned addr) {
    asm volatile("ldmatrix.sync.aligned.m8n8.x4.shared.b16 {%0,%1,%2,%3}, [%4];"
        : "=r"(r[0]), "=r"(r[1]), "=r"(r[2]), "=r"(r[3]) : "r"(addr));
}

// ---------------------------------------------------------------------------
// Fused weight pack: blockIdx.y selects {Wk->kv, Wv->kv(+off), Wq, W1}.
// ---------------------------------------------------------------------------
__global__ void __launch_bounds__(256)
pack_all_kernel(const float* __restrict__ Wk, const float* __restrict__ Wv,
                const float* __restrict__ Wq, const float* __restrict__ W1,
                uint2* __restrict__ wkvF, uint2* __restrict__ wqF,
                uint2* __restrict__ w1F)
{
    const int which = blockIdx.y;
    const float* W;
    uint2* out;
    int K, outNtiles, tnOff;
    switch (which) {
        case 0: W = Wk; out = wkvF; K = CT; outNtiles = NKV/8; tnOff = 0;    break;
        case 1: W = Wv; out = wkvF; K = CT; outNtiles = NKV/8; tnOff = CI/8; break;
        case 2: W = Wq; out = wqF;  K = CV; outNtiles = CI/8;  tnOff = 0;    break;
        default:W = W1; out = w1F;  K = CI; outNtiles = CI/8;  tnOff = 0;    break;
    }
    const int N = CI;
    const int idx = blockIdx.x * 256 + threadIdx.x;
    const int total = (K / 16) * (N / 8) * 32;
    if (idx >= total) return;
    const int lane = idx & 31;
    const int tile = idx >> 5;
    const int ntiles = N / 8;
    const int tn = tile % ntiles;
    const int tk = tile / ntiles;
    const int g = lane >> 2, tig = lane & 3;
    const int n = tn * 8 + g;
    const int k0 = tk * 16 + 2 * tig;
    const __half2 b0 = __floats2half2_rn(W[(size_t)k0 * N + n], W[(size_t)(k0 + 1) * N + n]);
    const __half2 b1 = __floats2half2_rn(W[(size_t)(k0 + 8) * N + n], W[(size_t)(k0 + 9) * N + n]);
    uint2 r;
    r.x = h2u(b0);
    r.y = h2u(b1);
    out[((size_t)tk * outNtiles + tnOff + tn) * 32 + lane] = r;
}

// ---------------------------------------------------------------------------
// FP16 mma.sync GEMM (R9/R11-proven structure — UNTOUCHED). Block 128x256,
// 8 warps, warp 64x64. A single-buffer smem + register staging, fragments via
// ldmatrix.x4; B fragment-order from global, register double-buffered.
// ---------------------------------------------------------------------------
#define AS2_STRIDE 20

template <bool AHALF, bool MLPHEAD>
__global__ void __launch_bounds__(256)
gemm_f16_kernel(const void* __restrict__ Aptr, const uint2* __restrict__ Bf,
                const float* __restrict__ bias, __half2* __restrict__ Ch,
                const float* __restrict__ W2, float* __restrict__ part,
                int M, int N, int K)
{
    __shared__ __half2 As[128 * AS2_STRIDE];
    __shared__ float red[4][128][2];   // only used when MLPHEAD

    const int tid = threadIdx.x;
    const int warp = tid >> 5, lane = tid & 31;
    const int g = lane >> 2, tig = lane & 3;
    const int wm = (warp >> 2) * 64;
    const int wnIdx = warp & 3;
    const int wn = wnIdx * 64;
    const int rowBase = blockIdx.y * 128;
    const int colBase = blockIdx.x * 256;
    const int Ntiles = N >> 3;
    const int tnBase = (colBase + wn) >> 3;

    const int lmRow = wm + (lane & 7) + ((lane >> 3) & 1) * 8;
    const int lmCol = (lane >> 4) * 4;
    const unsigned lmBase =
        (unsigned)__cvta_generic_to_shared(&As[lmRow * AS2_STRIDE + lmCol]);

    float acc[4][8][4];
#pragma unroll
    for (int mt = 0; mt < 4; mt++)
#pragma unroll
        for (int nt = 0; nt < 8; nt++)
#pragma unroll
            for (int r = 0; r < 4; r++) acc[mt][nt][r] = 0.f;

    const int KT = K >> 5;
    const int TKT = KT * 2;
    float4 ar[4];
    uint4 arh[2];

    auto ldg_a = [&](int kt) {
        if (AHALF) {
            const __half2* Ah = (const __half2*)Aptr;
#pragma unroll
            for (int i = 0; i < 2; i++) {
                const int f = tid + i * 256;
                const int r = f >> 2, c4 = (f & 3) * 4;
                arh[i] = *(const uint4*)(Ah + (size_t)(rowBase + r) * (K / 2) + kt * 16 + c4);
            }
        } else {
            const float* Af = (const float*)Aptr;
#pragma unroll
            for (int i = 0; i < 4; i++) {
                const int f = tid + i * 256;
                const int r = f >> 3, c4 = (f & 7) * 4;
                ar[i] = *(const float4*)(Af + (size_t)(rowBase + r) * K + kt * 32 + c4);
            }
        }
    };

    uint2 bfr[2][8];
    {   // preload B fragments for tk = 0
        const uint2* bp = Bf + (size_t)tnBase * 32 + lane;
#pragma unroll
        for (int nt = 0; nt < 8; nt++) bfr[0][nt] = bp[nt * 32];
    }
    ldg_a(0);

    for (int kt = 0; kt < KT; kt++) {
        if (kt) __syncthreads();
        if (AHALF) {
#pragma unroll
            for (int i = 0; i < 2; i++) {
                const int f = tid + i * 256;
                const int r = f >> 2, c4 = (f & 3) * 4;
                *(uint4*)&As[r * AS2_STRIDE + c4] = arh[i];
            }
        } else {
#pragma unroll
            for (int i = 0; i < 4; i++) {
                const int f = tid + i * 256;
                const int r = f >> 3, c2 = (f & 7) * 2;
                const __half2 h0 = __floats2half2_rn(ar[i].x, ar[i].y);
                const __half2 h1 = __floats2half2_rn(ar[i].z, ar[i].w);
                __half2* dst = &As[r * AS2_STRIDE + c2];
                dst[0] = h0; dst[1] = h1;
            }
        }
        __syncthreads();

        if (kt + 1 < KT) ldg_a(kt + 1);

#pragma unroll
        for (int k16 = 0; k16 < 2; k16++) {
            const int tk = kt * 2 + k16;
            const int cur = tk & 1;
            if (tk + 1 < TKT) {
                const uint2* bp = Bf + ((size_t)(tk + 1) * Ntiles + tnBase) * 32 + lane;
#pragma unroll
                for (int nt = 0; nt < 8; nt++) bfr[cur ^ 1][nt] = bp[nt * 32];
            }
            unsigned a[4][4];
            const unsigned kOff = k16 * 8 * 4;
#pragma unroll
            for (int mt = 0; mt < 4; mt++)
                ldmatrix_x4(a[mt], lmBase + mt * 16 * AS2_STRIDE * 4 + kOff);
#pragma unroll
            for (int mt = 0; mt < 4; mt++)
#pragma unroll
                for (int nt = 0; nt < 8; nt++)
                    mma_f16(acc[mt][nt], a[mt], (const unsigned*)&bfr[cur][nt]);
        }
    }

    if (!MLPHEAD) {
        const int Nh = N >> 1;
#pragma unroll
        for (int mt = 0; mt < 4; mt++) {
            const int r0 = rowBase + wm + mt * 16 + g;
            const int r1 = r0 + 8;
#pragma unroll
            for (int nt = 0; nt < 8; nt++) {
                const int c = colBase + wn + nt * 8 + tig * 2;
                const float b0 = bias[c], b1 = bias[c + 1];
                Ch[(size_t)r0 * Nh + (c >> 1)] =
                    __floats2half2_rn(acc[mt][nt][0] + b0, acc[mt][nt][1] + b1);
                Ch[(size_t)r1 * Nh + (c >> 1)] =
                    __floats2half2_rn(acc[mt][nt][2] + b0, acc[mt][nt][3] + b1);
            }
        }
    } else {
#pragma unroll
        for (int mt = 0; mt < 4; mt++) {
            float h00 = 0.f, h01 = 0.f, h10 = 0.f, h11 = 0.f;
#pragma unroll
            for (int nt = 0; nt < 8; nt++) {
                const int c = colBase + wn + nt * 8 + tig * 2;
                const float b0 = bias[c], b1 = bias[c + 1];
                float v00 = acc[mt][nt][0] + b0, v01 = acc[mt][nt][1] + b1;
                float v10 = acc[mt][nt][2] + b0, v11 = acc[mt][nt][3] + b1;
                v00 = v00 / (1.f + __expf(-1.702f * v00));
                v01 = v01 / (1.f + __expf(-1.702f * v01));
                v10 = v10 / (1.f + __expf(-1.702f * v10));
                v11 = v11 / (1.f + __expf(-1.702f * v11));
                const float4 w4 = *(const float4*)(W2 + 2 * c);
                h00 += v00 * w4.x + v01 * w4.z;
                h01 += v00 * w4.y + v01 * w4.w;
                h10 += v10 * w4.x + v11 * w4.z;
                h11 += v10 * w4.y + v11 * w4.w;
            }
#pragma unroll
            for (int o = 1; o <= 2; o <<= 1) {
                h00 += __shfl_xor_sync(0xffffffff, h00, o);
                h01 += __shfl_xor_sync(0xffffffff, h01, o);
                h10 += __shfl_xor_sync(0xffffffff, h10, o);
                h11 += __shfl_xor_sync(0xffffffff, h11, o);
            }
            if (tig == 0) {
                const int rl = wm + mt * 16 + g;
                red[wnIdx][rl][0] = h00; red[wnIdx][rl][1] = h01;
                red[wnIdx][rl + 8][0] = h10; red[wnIdx][rl + 8][1] = h11;
            }
        }
        __syncthreads();
        const int rl = tid >> 1, o = tid & 1;
        const float s = red[0][rl][o] + red[1][rl][o] + red[2][rl][o] + red[3][rl][o];
        part[(size_t)blockIdx.x * MQ * 2 + (size_t)(rowBase + rl) * 2 + o] = s;
    }
}

// ---------------------------------------------------------------------------
// Tensor-core attention + residual. TWO blocks per (b,h) (R12 layout).
// CHANGE vs R12: epilogue goes through a small per-warp smem stage so the
// vis loads (256B) and fused stores (128B) are fully coalesced. ~34.6 KB smem.
// ---------------------------------------------------------------------------
#define STG_STRIDE 36

__global__ void __launch_bounds__(128)
attn_kernel(const __half2* __restrict__ qh, const __half2* __restrict__ kvh,
            const float* __restrict__ vis, __half2* __restrict__ fusedh)
{
    __shared__ __half2 Qs[112 * 36];
    __shared__ __half2 Ks[32 * 36];
    __shared__ __half2 Vs[16 * 72];
    __shared__ __half2 Stage[4][16 * STG_STRIDE];

    const int bh = blockIdx.x >> 1;
    const int chunk = blockIdx.x & 1;
    const int b = bh / NHEAD;
    const int h = bh % NHEAD;
    const int tid = threadIdx.x;
    const int warp = tid >> 5, lane = tid & 31;
    const int g = lane >> 2, tig = lane & 3;

    const int chunkBase = chunk * 112;
    const int nRows = chunk ? (NV - 112) : 112;
    const int numTiles = chunk ? 6 : 7;

    for (int f = tid; f < nRows * 8; f += 128) {
        const int n = f >> 3, c = f & 7;
        *(uint4*)&Qs[n * 36 + c * 4] =
            *(const uint4*)(qh + ((size_t)b * NV + chunkBase + n) * 384 + h * 32 + c * 4);
    }
    const int padRows = numTiles * 16 - nRows;
    for (int f = tid; f < padRows * 36; f += 128) {
        Qs[nRows * 36 + f] = __half2(__ushort_as_half(0), __ushort_as_half(0));
    }
    for (int f = tid; f < 32 * 8; f += 128) {
        const int l = f >> 3, c = f & 7;
        *(uint4*)&Ks[l * 36 + c * 4] =
            *(const uint4*)(kvh + ((size_t)b * LT + l) * 768 + h * 32 + c * 4);
    }
    __half* Vsh = (__half*)Vs;
    for (int f = tid; f < 32 * 32; f += 128) {
        const int l = f >> 5, d2 = f & 31;
        const __half2 val = kvh[((size_t)b * LT + l) * 768 + 384 + h * 32 + d2];
        const int base = (l >> 1) * 144 + 4 * d2 + (l & 1);
        Vsh[base] = __low2half(val);
        Vsh[base + 2] = __high2half(val);
    }
    __syncthreads();

    for (int t = warp; t < numTiles; t += 4) {
        const int mb = t * 16;
        float sc[4][4];
#pragma unroll
        for (int tl = 0; tl < 4; tl++)
#pragma unroll
            for (int j = 0; j < 4; j++) sc[tl][j] = 0.f;
#pragma unroll
        for (int td = 0; td < 4; td++) {
            unsigned a[4];
            a[0] = *(const unsigned*)&Qs[(mb + g) * 36 + 8 * td + tig];
            a[1] = *(const unsigned*)&Qs[(mb + 8 + g) * 36 + 8 * td + tig];
            a[2] = *(const unsigned*)&Qs[(mb + g) * 36 + 8 * td + tig + 4];
            a[3] = *(const unsigned*)&Qs[(mb + 8 + g) * 36 + 8 * td + tig + 4];
#pragma unroll
            for (int tl = 0; tl < 4; tl++) {
                unsigned bb[2];
                bb[0] = *(const unsigned*)&Ks[(8 * tl + g) * 36 + 8 * td + tig];
                bb[1] = *(const unsigned*)&Ks[(8 * tl + g) * 36 + 8 * td + tig + 4];
                mma_f16(sc[tl], a, bb);
            }
        }
        float mx0 = -1e30f, mx1 = -1e30f;
#pragma unroll
        for (int tl = 0; tl < 4; tl++) {
#pragma unroll
            for (int j = 0; j < 4; j++) sc[tl][j] *= 0.125f;
            mx0 = fmaxf(mx0, fmaxf(sc[tl][0], sc[tl][1]));
            mx1 = fmaxf(mx1, fmaxf(sc[tl][2], sc[tl][3]));
        }
        mx0 = fmaxf(mx0, __shfl_xor_sync(0xffffffff, mx0, 1));
        mx0 = fmaxf(mx0, __shfl_xor_sync(0xffffffff, mx0, 2));
        mx1 = fmaxf(mx1, __shfl_xor_sync(0xffffffff, mx1, 1));
        mx1 = fmaxf(mx1, __shfl_xor_sync(0xffffffff, mx1, 2));
        __half2 plo[4], phi[4];
        float sum0 = 0.f, sum1 = 0.f;
#pragma unroll
        for (int tl = 0; tl < 4; tl++) {
            const __half2 e0 = h2exp(__floats2half2_rn(sc[tl][0] - mx0, sc[tl][1] - mx0));
            const __half2 e1 = h2exp(__floats2half2_rn(sc[tl][2] - mx1, sc[tl][3] - mx1));
            plo[tl] = e0; phi[tl] = e1;
            const float2 f0 = __half22float2(e0);
            const float2 f1 = __half22float2(e1);
            sum0 += f0.x + f0.y;
            sum1 += f1.x + f1.y;
        }
        sum0 += __shfl_xor_sync(0xffffffff, sum0, 1);
        sum0 += __shfl_xor_sync(0xffffffff, sum0, 2);
        sum1 += __shfl_xor_sync(0xffffffff, sum1, 1);
        sum1 += __shfl_xor_sync(0xffffffff, sum1, 2);
        const float inv0 = __fdividef(1.f, sum0);
        const float inv1 = __fdividef(1.f, sum1);
        float cc[8][4];
#pragma unroll
        for (int tn = 0; tn < 8; tn++)
#pragma unroll
            for (int j = 0; j < 4; j++) cc[tn][j] = 0.f;
#pragma unroll
        for (int tl2 = 0; tl2 < 2; tl2++) {
            unsigned a[4];
            a[0] = h2u(plo[2 * tl2]);
            a[1] = h2u(phi[2 * tl2]);
            a[2] = h2u(plo[2 * tl2 + 1]);
            a[3] = h2u(phi[2 * tl2 + 1]);
#pragma unroll
            for (int tn = 0; tn < 8; tn++) {
                unsigned bb[2];
                bb[0] = *(const unsigned*)&Vs[(8 * tl2 + tig) * 72 + 8 * tn + g];
                bb[1] = *(const unsigned*)&Vs[(8 * tl2 + tig + 4) * 72 + 8 * tn + g];
                mma_f16(cc[tn], a, bb);
            }
        }

        // --- coalesced epilogue via per-warp smem stage ---
        __half2* st = Stage[warp];
#pragma unroll
        for (int tn = 0; tn < 8; tn++) {
            const int c2 = 4 * tn + tig;
            st[g * STG_STRIDE + c2] =
                __floats2half2_rn(cc[tn][0] * inv0, cc[tn][1] * inv0);
            st[(g + 8) * STG_STRIDE + c2] =
                __floats2half2_rn(cc[tn][2] * inv1, cc[tn][3] * inv1);
        }
        __syncwarp();
#pragma unroll
        for (int rr = 0; rr < 16; rr++) {
            const int gr = chunkBase + mb + rr;
            if (gr < NV) {
                const size_t row = (size_t)b * NV + gr;
                const float2 v = *(const float2*)(vis + row * CV + h * 64 + 2 * lane);
                fusedh[row * 384 + h * 32 + lane] =
                    __hadd2(st[rr * STG_STRIDE + lane], __floats2half2_rn(v.x, v.y));
            }
        }
        __syncwarp();
    }
}

// ---------------------------------------------------------------------------
// Output finalize: logits = b2 + 3 stripe partials; rel = 1/32.
// ---------------------------------------------------------------------------
__global__ void __launch_bounds__(256)
finalize_kernel(const float* __restrict__ part, const float* __restrict__ b2,
                float* __restrict__ out)
{
    const int idx = blockIdx.x * 256 + threadIdx.x;
    if (idx < MQ * 2) {
        const int o = idx & 1;
        out[idx] = b2[o] + part[idx] + part[(size_t)MQ * 2 + idx]
                 + part[(size_t)2 * MQ * 2 + idx];
    } else if (idx < MQ * 3) {
        out[idx] = 0.03125f;
    }
}

// ---------------------------------------------------------------------------
extern "C" void kernel_launch(void* const* d_in, const int* in_sizes, int n_in,
                              void* d_out, int out_size)
{
    const float* vis  = (const float*)d_in[0];
    const float* text = (const float*)d_in[1];
    const float* Wq = (const float*)d_in[2];
    const float* bq = (const float*)d_in[3];
    const float* Wk = (const float*)d_in[4];
    const float* bk = (const float*)d_in[5];
    const float* Wv = (const float*)d_in[6];
    const float* bv = (const float*)d_in[7];
    const float* W1 = (const float*)d_in[8];
    const float* b1 = (const float*)d_in[9];
    const float* W2 = (const float*)d_in[10];
    const float* b2 = (const float*)d_in[11];
    float* out = (float*)d_out;

    __half2 *qh, *kvh, *fusedh;
    float *partp, *bkv;
    uint2 *wkvF, *wqF, *w1F;
    cudaGetSymbolAddress((void**)&qh,     g_qh);
    cudaGetSymbolAddress((void**)&kvh,    g_kvh);
    cudaGetSymbolAddress((void**)&fusedh, g_fusedh);
    cudaGetSymbolAddress((void**)&partp,  g_part);
    cudaGetSymbolAddress((void**)&wkvF,   g_wkvF);
    cudaGetSymbolAddress((void**)&wqF,    g_wqF);
    cudaGetSymbolAddress((void**)&w1F,    g_w1F);
    cudaGetSymbolAddress((void**)&bkv,    g_bkv);

    pack_all_kernel<<<dim3(576, 4), 256>>>(Wk, Wv, Wq, W1, wkvF, wqF, w1F);
    cudaMemcpyAsync(bkv,      bk, CI * sizeof(float), cudaMemcpyDeviceToDevice);
    cudaMemcpyAsync(bkv + CI, bv, CI * sizeof(float), cudaMemcpyDeviceToDevice);

    gemm_f16_kernel<false, false><<<dim3(NKV / 256, MKV / 128), 256>>>(
        text, wkvF, bkv, kvh, nullptr, nullptr, MKV, NKV, CT);
    gemm_f16_kernel<false, false><<<dim3(CI / 256, MQ / 128), 256>>>(
        vis, wqF, bq, qh, nullptr, nullptr, MQ, CI, CV);
    attn_kernel<<<BATCH * NHEAD * 2, 128>>>(qh, kvh, vis, fusedh);
    gemm_f16_kernel<true, true><<<dim3(CI / 256, MQ / 128), 256>>>(
        fusedh, w1F, b1, nullptr, W2, partp, MQ, CI, CI);
    finalize_kernel<<<(MQ * 3 + 255) / 256, 256>>>(partp, b2, out);
}